// round 16
// baseline (speedup 1.0000x reference)
#include <cuda_runtime.h>
#include <cstdint>

// MaskLayer: per-(batch,channel) spatial argmax -> L1-distance mask -> scale.
// x, out: [B, 14, 14, 512] float32, channel-innermost.
//
// R14 = record kernel (R5: one-shot CTAs, DTILE=64, 50KB smem, 4 CTAs/SM,
// cp.async.cg loads) with ONE new mechanism: bulk-async stores.
// Phase C writes masked values back into the smem tile in place, then each
// 256B-contiguous spatial row is stored to gmem with a single
// cp.async.bulk.global.shared::cta op (196 per CTA) — the async copy engine
// forms guaranteed full-256B write bursts and store issue leaves the warps.
// This is the only memory path not yet tested (read-path TMA==LDG was
// measured path-independent; the write path was not).

static constexpr int IMGS     = 14;
static constexpr int SPATIAL  = IMGS * IMGS;              // 196
static constexpr int DEPTH    = 512;
static constexpr int DTILE    = 64;                       // channels per CTA
static constexpr int BLOCK    = 128;
static constexpr int TILE_FLOATS = SPATIAL * DTILE;       // 12544
static constexpr int TILE_VEC4   = TILE_FLOATS / 4;       // 3136
static constexpr int ITERS    = (TILE_VEC4 + BLOCK - 1) / BLOCK;  // 25 (last: warps 0-1)
static constexpr int SMEM_BYTES = TILE_FLOATS * (int)sizeof(float);  // 50176
static constexpr int ROW_BYTES = DTILE * (int)sizeof(float);         // 256

static constexpr float NEG_BIG = -3.402823466e38f;

__device__ __forceinline__ uint32_t smem_u32(const void* p) {
    return (uint32_t)__cvta_generic_to_shared(p);
}

__global__ void __launch_bounds__(BLOCK, 4)
mask_layer_kernel(const float* __restrict__ x, float* __restrict__ out) {
    extern __shared__ __align__(256) float tile[];   // [SPATIAL][DTILE]
    __shared__ int sidx[DTILE];            // packed (row | col<<16) per channel

    const int tid = threadIdx.x;
    const int dt  = blockIdx.x & 7;        // DEPTH / DTILE = 8 tiles per batch
    const int b   = blockIdx.x >> 3;
    const size_t base = (size_t)b * (SPATIAL * DEPTH) + (size_t)dt * DTILE;
    const float* __restrict__ src = x + base;

    // ---- Phase A: stage tile via cp.async.cg (16B, L1-bypass) ----
    // idx -> (s = idx>>4, c4 = (idx&15)*4). Each spatial position is 256B
    // contiguous in gmem; a warp covers 2 positions (512B). Smem conflict-free.
#pragma unroll
    for (int k = 0; k < ITERS; k++) {
        int idx = tid + k * BLOCK;
        if (idx < TILE_VEC4) {             // warp-uniform (k=24: warps 0-1 only)
            int s  = idx >> 4;
            int c4 = (idx & 15) << 2;
            uint32_t d = smem_u32(tile + s * DTILE + c4);
            const float* g = src + (size_t)s * DEPTH + c4;
            asm volatile("cp.async.cg.shared.global [%0], [%1], 16;\n"
                         :: "r"(d), "l"(g));
        }
    }
    asm volatile("cp.async.commit_group;\ncp.async.wait_group 0;\n" ::: "memory");
    __syncthreads();

    // ---- Phase B: per-channel argmax(rowmax) / argmax(colmax) ----
    // 128 threads / 64 channels: both halves redundantly compute channel
    // c = tid & 63 (conflict-free LDS, no combine needed).
    // Strict '>' with ascending index == jnp.argmax first-occurrence.
    {
        const int c = tid & (DTILE - 1);
        float colmax[IMGS];
#pragma unroll
        for (int j = 0; j < IMGS; j++) colmax[j] = NEG_BIG;

        float bestRow = NEG_BIG;
        int rowIdx = 0;
#pragma unroll 2
        for (int i = 0; i < IMGS; i++) {
            float rmax = NEG_BIG;
#pragma unroll
            for (int j = 0; j < IMGS; j++) {
                float v = tile[(i * IMGS + j) * DTILE + c];
                rmax = fmaxf(rmax, v);
                colmax[j] = fmaxf(colmax[j], v);
            }
            if (rmax > bestRow) { bestRow = rmax; rowIdx = i; }
        }
        int colIdx = 0;
        float bestCol = colmax[0];
#pragma unroll
        for (int j = 1; j < IMGS; j++)
            if (colmax[j] > bestCol) { bestCol = colmax[j]; colIdx = j; }

        if (tid < DTILE) sidx[c] = rowIdx | (colIdx << 16);
    }
    __syncthreads();

    // ---- Phase C: apply mask IN PLACE in smem ----
    // Each element is read exactly once by its owning thread before that
    // thread overwrites the same address; threads touch disjoint quads.
    const float TAUF = 0.5f / 196.0f;               // TAU
    const float TC   = TAUF * (4.0f / 14.0f);       // TAU * BETA / IMG_SIZE

#pragma unroll 5
    for (int k = 0; k < ITERS; k++) {
        int idx = tid + k * BLOCK;
        if (idx < TILE_VEC4) {
            int s  = idx >> 4;
            int c4 = (idx & 15) << 2;
            int i  = s / IMGS;
            int j  = s - i * IMGS;

            float4 v = *(const float4*)(tile + s * DTILE + c4);
            int4   p = *(const int4*)(sidx + c4);

            // mask = TAU*max(1 - COEF*l1, -1) = max(TAU - (TAU*COEF)*l1, -TAU)
            auto msk = [&](int pk) -> float {
                int r  = pk & 0xFFFF;
                int cc = pk >> 16;
                int l1 = abs(i - r) + abs(j - cc);
                return fmaxf(fmaf((float)l1, -TC, TAUF), -TAUF);
            };

            float4 o;
            o.x = msk(p.x) * v.x;
            o.y = msk(p.y) * v.y;
            o.z = msk(p.z) * v.z;
            o.w = msk(p.w) * v.w;
            *(float4*)(tile + s * DTILE + c4) = o;   // in-place
        }
    }
    __syncthreads();
    // Order the generic-proxy STS above before the async-proxy bulk reads.
    asm volatile("fence.proxy.async.shared::cta;" ::: "memory");

    // ---- Phase D: bulk-async stores, one 256B op per spatial position ----
    {
        float* __restrict__ dstg = out + base;
#pragma unroll 2
        for (int s = tid; s < SPATIAL; s += BLOCK) {   // threads 0-67 do 2
            asm volatile(
                "cp.async.bulk.global.shared::cta.bulk_group [%0], [%1], %2;\n"
                :: "l"(dstg + (size_t)s * DEPTH),
                   "r"(smem_u32(tile + s * DTILE)),
                   "n"(ROW_BYTES)
                : "memory");
        }
        asm volatile("cp.async.bulk.commit_group;\n" ::: "memory");
        asm volatile("cp.async.bulk.wait_group 0;\n" ::: "memory");
    }
}

extern "C" void kernel_launch(void* const* d_in, const int* in_sizes, int n_in,
                              void* d_out, int out_size) {
    (void)n_in; (void)out_size;
    const float* x = (const float*)d_in[0];
    float* out = (float*)d_out;

    int n = in_sizes[0];                                  // B * 196 * 512
    int batches = n / (SPATIAL * DEPTH);                  // 1024
    int grid = batches * (DEPTH / DTILE);                 // 8192

    // Host-side attribute call: immediate, deterministic, capture-safe.
    cudaFuncSetAttribute(mask_layer_kernel,
                         cudaFuncAttributeMaxDynamicSharedMemorySize, SMEM_BYTES);

    mask_layer_kernel<<<grid, BLOCK, SMEM_BYTES>>>(x, out);
}

// round 17
// speedup vs baseline: 1.0485x; 1.0485x over previous
#include <cuda_runtime.h>
#include <cstdint>

// MaskLayer: per-(batch,channel) spatial argmax -> L1-distance mask -> scale.
// x, out: [B, 14, 14, 512] float32, channel-innermost.
//
// FINAL (record holder, measured 121.312us twice, reproduced 121.57):
// one-shot CTAs, DTILE=64 -> 50KB smem -> 4 CTAs/SM (launch_bounds(128,4)).
// cp.async.cg staging (single compulsory DRAM read), smem-resident
// per-channel argmax reduction, plain fully-coalesced STG.128 stores.
//
// Convergence ledger (11 kernels): occupancy 24/47/96%, issue-diet, phase
// decorrelation, persistent loops, explicit double-buffering, L2::256B
// hints all land at 83-85% DRAM / 121.3-121.9us. Regressions: __stcs (-9%
// DRAM), 1-CTA/SM explicit pipeline (-9%), bulk-async stores (-6%). Both
// read and write paths measured path-independent at the LTS/HBM ceiling.
// 822MB compulsory 1:1 R/W traffic at ~7.1TB/s effective mixed-stream
// throughput == this part's HBM turnaround roofline. This kernel sits at it.

static constexpr int IMGS     = 14;
static constexpr int SPATIAL  = IMGS * IMGS;              // 196
static constexpr int DEPTH    = 512;
static constexpr int DTILE    = 64;                       // channels per CTA
static constexpr int BLOCK    = 128;
static constexpr int TILE_FLOATS = SPATIAL * DTILE;       // 12544
static constexpr int TILE_VEC4   = TILE_FLOATS / 4;       // 3136
static constexpr int ITERS    = (TILE_VEC4 + BLOCK - 1) / BLOCK;  // 25 (last: warps 0-1)
static constexpr int SMEM_BYTES = TILE_FLOATS * (int)sizeof(float);  // 50176

static constexpr float NEG_BIG = -3.402823466e38f;

__device__ __forceinline__ uint32_t smem_u32(const void* p) {
    return (uint32_t)__cvta_generic_to_shared(p);
}

__global__ void __launch_bounds__(BLOCK, 4)
mask_layer_kernel(const float* __restrict__ x, float* __restrict__ out) {
    extern __shared__ float tile[];        // [SPATIAL][DTILE]
    __shared__ int sidx[DTILE];            // packed (row | col<<16) per channel

    const int tid = threadIdx.x;
    const int dt  = blockIdx.x & 7;        // DEPTH / DTILE = 8 tiles per batch
    const int b   = blockIdx.x >> 3;
    const size_t base = (size_t)b * (SPATIAL * DEPTH) + (size_t)dt * DTILE;
    const float* __restrict__ src = x + base;

    // ---- Phase A: stage tile via cp.async.cg (16B, L1-bypass) ----
    // idx -> (s = idx>>4, c4 = (idx&15)*4). Each spatial position is 256B
    // contiguous in gmem; a warp covers 2 positions (512B). Smem conflict-free.
#pragma unroll
    for (int k = 0; k < ITERS; k++) {
        int idx = tid + k * BLOCK;
        if (idx < TILE_VEC4) {             // warp-uniform (k=24: warps 0-1 only)
            int s  = idx >> 4;
            int c4 = (idx & 15) << 2;
            uint32_t d = smem_u32(tile + s * DTILE + c4);
            const float* g = src + (size_t)s * DEPTH + c4;
            asm volatile("cp.async.cg.shared.global [%0], [%1], 16;\n"
                         :: "r"(d), "l"(g));
        }
    }
    asm volatile("cp.async.commit_group;\ncp.async.wait_group 0;\n" ::: "memory");
    __syncthreads();

    // ---- Phase B: per-channel argmax(rowmax) / argmax(colmax) ----
    // 128 threads / 64 channels: both halves redundantly compute channel
    // c = tid & 63 (conflict-free LDS, no combine needed).
    // Strict '>' with ascending index == jnp.argmax first-occurrence.
    {
        const int c = tid & (DTILE - 1);
        float colmax[IMGS];
#pragma unroll
        for (int j = 0; j < IMGS; j++) colmax[j] = NEG_BIG;

        float bestRow = NEG_BIG;
        int rowIdx = 0;
#pragma unroll 2
        for (int i = 0; i < IMGS; i++) {
            float rmax = NEG_BIG;
#pragma unroll
            for (int j = 0; j < IMGS; j++) {
                float v = tile[(i * IMGS + j) * DTILE + c];
                rmax = fmaxf(rmax, v);
                colmax[j] = fmaxf(colmax[j], v);
            }
            if (rmax > bestRow) { bestRow = rmax; rowIdx = i; }
        }
        int colIdx = 0;
        float bestCol = colmax[0];
#pragma unroll
        for (int j = 1; j < IMGS; j++)
            if (colmax[j] > bestCol) { bestCol = colmax[j]; colIdx = j; }

        if (tid < DTILE) sidx[c] = rowIdx | (colIdx << 16);
    }
    __syncthreads();

    // ---- Phase C: apply mask, vectorized 16B stores ----
    const float TAUF = 0.5f / 196.0f;               // TAU
    const float TC   = TAUF * (4.0f / 14.0f);       // TAU * BETA / IMG_SIZE
    float* __restrict__ dstg = out + base;

#pragma unroll 5
    for (int k = 0; k < ITERS; k++) {
        int idx = tid + k * BLOCK;
        if (idx < TILE_VEC4) {
            int s  = idx >> 4;
            int c4 = (idx & 15) << 2;
            int i  = s / IMGS;
            int j  = s - i * IMGS;

            float4 v = *(const float4*)(tile + s * DTILE + c4);
            int4   p = *(const int4*)(sidx + c4);

            // mask = TAU*max(1 - COEF*l1, -1) = max(TAU - (TAU*COEF)*l1, -TAU)
            auto msk = [&](int pk) -> float {
                int r  = pk & 0xFFFF;
                int cc = pk >> 16;
                int l1 = abs(i - r) + abs(j - cc);
                return fmaxf(fmaf((float)l1, -TC, TAUF), -TAUF);
            };

            float4 o;
            o.x = msk(p.x) * v.x;
            o.y = msk(p.y) * v.y;
            o.z = msk(p.z) * v.z;
            o.w = msk(p.w) * v.w;
            *(float4*)(dstg + (size_t)s * DEPTH + c4) = o;
        }
    }
}

extern "C" void kernel_launch(void* const* d_in, const int* in_sizes, int n_in,
                              void* d_out, int out_size) {
    (void)n_in; (void)out_size;
    const float* x = (const float*)d_in[0];
    float* out = (float*)d_out;

    int n = in_sizes[0];                                  // B * 196 * 512
    int batches = n / (SPATIAL * DEPTH);                  // 1024
    int grid = batches * (DEPTH / DTILE);                 // 8192

    // Host-side attribute call: immediate, deterministic, capture-safe.
    cudaFuncSetAttribute(mask_layer_kernel,
                         cudaFuncAttributeMaxDynamicSharedMemorySize, SMEM_BYTES);

    mask_layer_kernel<<<grid, BLOCK, SMEM_BYTES>>>(x, out);
}